// round 17
// baseline (speedup 1.0000x reference)
#include <cuda_runtime.h>
#include <cuda_bf16.h>
#include <cstdint>
#include <math.h>

// ---------------------------------------------------------------------------
// ann2_snn1 — bit-faithful emulation of the JAX/XLA-CPU reference (verified
// rel_err == 0.0). Numerics contract (must not change):
//  * every dot product: ONE f32 accumulator, strictly ascending k, IEEE RN FMA
//    (fma.rn.f32x2 = two INDEPENDENT IEEE lanes — validated exact in R8)
//  * elementwise ops: separate f32 rounds in reference order
//  * logistic = 0.5 + 0.5*tanh(0.5x) with XLA's rational tanh
// ---------------------------------------------------------------------------

#define BATCH 1024
#define HID   500
#define NIN   784
#define NOUT  10
#define TLEN  100
#define NPASS 4
#define PASS_B (BATCH / NPASS)          // 256 batch elements per pass
#define PASS_ROWS (PASS_B * TLEN)       // 25600 psp rows per pass

__device__ float g_h[BATCH * HID];
__device__ float g_drive[BATCH * HID];
__device__ float g_psp[PASS_B * TLEN * HID];   // 51.2 MB slab (L2-resident)
__device__ float g_cur[BATCH * TLEN * NOUT];   // [b][t][j] pre-bias dots

#define A1F ((float)1.1466802242428472)    // exp(-1/4)+exp(-1)
#define A2F ((float)-0.28650479686019009)  // -exp(-1/4)*exp(-1)
#define SGF ((float)0.77880078307140487)   // exp(-1/4)

typedef unsigned long long ull;

__device__ __forceinline__ void ffma2(ull& d, ull a, ull b)
{
    asm("fma.rn.f32x2 %0, %1, %2, %0;" : "+l"(d) : "l"(a), "l"(b));
}
__device__ __forceinline__ ull splat2(float x)
{
    ull r;
    unsigned int u = __float_as_uint(x);
    asm("mov.b64 %0, {%1, %2};" : "=l"(r) : "r"(u), "r"(u));
    return r;
}
__device__ __forceinline__ void unpack2(ull v, float& lo, float& hi)
{
    unsigned int a, b;
    asm("mov.b64 {%0, %1}, %2;" : "=r"(a), "=r"(b) : "l"(v));
    lo = __uint_as_float(a);
    hi = __uint_as_float(b);
}

__device__ __forceinline__ float xla_tanh_f32(float x)
{
    const float kMax = 7.90531110763549805f;
    float xc = fminf(fmaxf(x, -kMax), kMax);
    float x2 = __fmul_rn(xc, xc);
    float p = -2.76076847742355e-16f;
    p = __fadd_rn(__fmul_rn(p, x2), 2.00018790482477e-13f);
    p = __fadd_rn(__fmul_rn(p, x2), -8.60467152213735e-11f);
    p = __fadd_rn(__fmul_rn(p, x2), 5.12229709037114e-08f);
    p = __fadd_rn(__fmul_rn(p, x2), 1.48572235717979e-05f);
    p = __fadd_rn(__fmul_rn(p, x2), 6.37261928875436e-04f);
    p = __fadd_rn(__fmul_rn(p, x2), 4.89352455891786e-03f);
    float num = __fmul_rn(xc, p);
    float q = 1.19825839466702e-06f;
    q = __fadd_rn(__fmul_rn(q, x2), 1.18534705686654e-04f);
    q = __fadd_rn(__fmul_rn(q, x2), 2.26843463243900e-03f);
    q = __fadd_rn(__fmul_rn(q, x2), 4.89352518554385e-03f);
    float r = __fdiv_rn(num, q);
    return (fabsf(x) < 0.0004f) ? x : r;
}

__device__ __forceinline__ float xla_sigmoid(float x)
{
    float t = xla_tanh_f32(__fmul_rn(0.5f, x));
    return __fadd_rn(0.5f, __fmul_rn(0.5f, t));
}

// ---- cp.async helpers ----
__device__ __forceinline__ void cp_async16(unsigned int smem_dst,
                                           const void* gsrc, int src_bytes)
{
    asm volatile("cp.async.cg.shared.global [%0], [%1], 16, %2;"
                 :: "r"(smem_dst), "l"(gsrc), "r"(src_bytes));
}
__device__ __forceinline__ void cp_commit()
{
    asm volatile("cp.async.commit_group;");
}
template<int N>
__device__ __forceinline__ void cp_wait()
{
    asm volatile("cp.async.wait_group %0;" :: "n"(N));
}

// ---------------------------------------------------------------------------
// cp.async 4-stage pipelined SGEMM (R14 winner — unchanged).
// ---------------------------------------------------------------------------
#define BM 64
#define BN 32
#define BK 16
#define NSTAGE 4
#define A_STRIDE 16
#define W_STRIDE 20
#define A_TILE (BM * A_STRIDE)
#define W_TILE (BN * W_STRIDE)

template<int ACT>
__global__ __launch_bounds__(128)
void gemm_bias_act(const float* __restrict__ A, const float* __restrict__ W,
                   const float* __restrict__ bias, float* __restrict__ C,
                   int M, int N, int K)
{
    __shared__ float As[NSTAGE][A_TILE];
    __shared__ float Ws[NSTAGE][W_TILE];

    const int tid = threadIdx.x;
    const int tx  = tid & 7;
    const int ty  = tid >> 3;
    const int bm  = blockIdx.y * BM;
    const int bn  = blockIdx.x * BN;

    const int T = (K + BK - 1) / BK;

    auto issue_stage = [&](int it) {
        const int s  = it & (NSTAGE - 1);
        const int kb = it * BK;
        unsigned int abase = (unsigned int)__cvta_generic_to_shared(&As[s][0]);
        unsigned int wbase = (unsigned int)__cvta_generic_to_shared(&Ws[s][0]);
        #pragma unroll
        for (int p = 0; p < 2; p++) {
            int idx = tid + p * 128;
            int m   = idx >> 2;
            int c   = idx & 3;
            int k0  = kb + c * 4;
            int rem = K - k0;
            int bytes = rem >= 4 ? 16 : (rem > 0 ? rem * 4 : 0);
            const float* src = A + (size_t)(bm + m) * K + (bytes ? k0 : 0);
            unsigned int dst = abase +
                (unsigned int)((m * A_STRIDE + ((c ^ ((m >> 2) & 3)) * 4)) * 4);
            cp_async16(dst, src, bytes);
        }
        {
            int n   = tid >> 2;
            int c   = tid & 3;
            int k0  = kb + c * 4;
            int wr  = bn + n;
            int rem = K - k0;
            int bytes = (wr < N) ? (rem >= 4 ? 16 : (rem > 0 ? rem * 4 : 0)) : 0;
            const float* src = W + (bytes ? ((size_t)wr * K + k0) : 0);
            unsigned int dst = wbase +
                (unsigned int)((n * W_STRIDE + ((c ^ ((n >> 3) & 3)) * 4)) * 4);
            cp_async16(dst, src, bytes);
        }
        cp_commit();
    };

    float acc[4][4] = {};

    issue_stage(0);
    if (T > 1) issue_stage(1);
    if (T > 2) issue_stage(2);

    const int asw = ty & 3;
    const int wsw = (tx >> 1) & 3;

    for (int it = 0; it < T; it++) {
        const int s = it & (NSTAGE - 1);
        if (it + 3 < T) issue_stage(it + 3);
        cp_wait<3>();
        __syncthreads();

        #pragma unroll
        for (int c = 0; c < 4; c++) {
            float4 a4[4], w4[4];
            const int ac = (c ^ asw) * 4;
            const int wc = (c ^ wsw) * 4;
            #pragma unroll
            for (int i = 0; i < 4; i++)
                a4[i] = *(const float4*)&As[s][(ty * 4 + i) * A_STRIDE + ac];
            #pragma unroll
            for (int j = 0; j < 4; j++)
                w4[j] = *(const float4*)&Ws[s][(tx * 4 + j) * W_STRIDE + wc];
            #pragma unroll
            for (int kk = 0; kk < 4; kk++) {
                float a[4] = { kk == 0 ? a4[0].x : kk == 1 ? a4[0].y : kk == 2 ? a4[0].z : a4[0].w,
                               kk == 0 ? a4[1].x : kk == 1 ? a4[1].y : kk == 2 ? a4[1].z : a4[1].w,
                               kk == 0 ? a4[2].x : kk == 1 ? a4[2].y : kk == 2 ? a4[2].z : a4[2].w,
                               kk == 0 ? a4[3].x : kk == 1 ? a4[3].y : kk == 2 ? a4[3].z : a4[3].w };
                float w[4] = { kk == 0 ? w4[0].x : kk == 1 ? w4[0].y : kk == 2 ? w4[0].z : w4[0].w,
                               kk == 0 ? w4[1].x : kk == 1 ? w4[1].y : kk == 2 ? w4[1].z : w4[1].w,
                               kk == 0 ? w4[2].x : kk == 1 ? w4[2].y : kk == 2 ? w4[2].z : w4[2].w,
                               kk == 0 ? w4[3].x : kk == 1 ? w4[3].y : kk == 2 ? w4[3].z : w4[3].w };
                #pragma unroll
                for (int i = 0; i < 4; i++)
                    #pragma unroll
                    for (int j = 0; j < 4; j++)
                        acc[i][j] = __fmaf_rn(a[i], w[j], acc[i][j]);
            }
        }
        __syncthreads();
    }

    const int n0 = bn + tx * 4;
    if (n0 < N) {
        float bv0 = bias[n0 + 0], bv1 = bias[n0 + 1];
        float bv2 = bias[n0 + 2], bv3 = bias[n0 + 3];
        #pragma unroll
        for (int i = 0; i < 4; i++) {
            int m = bm + ty * 4 + i;
            float x0 = __fadd_rn(acc[i][0], bv0);
            float x1 = __fadd_rn(acc[i][1], bv1);
            float x2 = __fadd_rn(acc[i][2], bv2);
            float x3 = __fadd_rn(acc[i][3], bv3);
            if (ACT == 0) {
                x0 = fmaxf(x0, 0.f); x1 = fmaxf(x1, 0.f);
                x2 = fmaxf(x2, 0.f); x3 = fmaxf(x3, 0.f);
            } else {
                x0 = xla_sigmoid(x0); x1 = xla_sigmoid(x1);
                x2 = xla_sigmoid(x2); x3 = xla_sigmoid(x3);
            }
            *(float4*)&C[(size_t)m * N + n0] = make_float4(x0, x1, x2, x3);
        }
    }
}

// ---------------------------------------------------------------------------
// S1: psp recurrence -> gmem slab (pass-local). One block per batch element,
// 256 threads (250 active, 2 columns each). Exact reference op order.
// Row writes are coalesced (250 consecutive floats per segment).
// ---------------------------------------------------------------------------
__global__ __launch_bounds__(256)
void psp_kernel(int pass)
{
    const int bl = blockIdx.x;              // pass-local batch index
    const int bg = pass * PASS_B + bl;      // global batch index
    const int tid = threadIdx.x;
    if (tid >= 250) return;

    const int k0 = tid, k1 = tid + 250;
    float d0 = g_drive[(size_t)bg * HID + k0];
    float d1 = g_drive[(size_t)bg * HID + k1];
    float p1a = 0.f, p2a = 0.f, p1b = 0.f, p2b = 0.f;
    float* base = g_psp + (size_t)bl * TLEN * HID;
    #pragma unroll 4
    for (int t = 0; t < TLEN; t++) {
        float pa = __fadd_rn(__fadd_rn(__fmul_rn(A1F, p1a),
                                       __fmul_rn(A2F, p2a)), d0);
        float pb = __fadd_rn(__fadd_rn(__fmul_rn(A1F, p1b),
                                       __fmul_rn(A2F, p2b)), d1);
        base[t * HID + k0] = pa;
        base[t * HID + k1] = pb;
        p2a = p1a; p1a = pa;
        p2b = p1b; p1b = pb;
    }
}

// ---------------------------------------------------------------------------
// S2: skinny GEMM  cur[r][j] = psp_row[r] . w3[j]  for r in one pass.
// 128 threads, thread = row, 10 j's as 5 f32x2 accumulators (independent
// IEEE lanes -> contract-safe, validated R8). psp tiles via the PROVEN
// cp.async 4-stage pipeline + XOR swizzle; w3 pre-interleaved into pair
// table in smem (warp-uniform broadcast reads). Zero-filled k-tail on the
// psp side; w3 pad zeroed (avoids 0*garbage=NaN).
// smem = 4*8KB tiles + 20KB pairs = 52.2KB -> 4 blocks/SM.
// ---------------------------------------------------------------------------
#define S2_BK 16
#define S2_T  ((HID + S2_BK - 1) / S2_BK)   // 32
#define S2_TILE (128 * S2_BK)               // 2048 floats per stage
#define SWP_LD 512

__global__ __launch_bounds__(128)
void dot_kernel(const float* __restrict__ w3g, float* __restrict__ curg,
                int pass)
{
    extern __shared__ float smem2[];
    float*  At  = smem2;                            // [4][2048]
    float2* swp = (float2*)(smem2 + 4 * S2_TILE);   // [5][512] pairs

    const int tid = threadIdx.x;
    const int rbase = blockIdx.x * 128;             // pass-local row base

    // stage interleaved weight pairs (pad k in [500,512) zeroed)
    for (int i = tid; i < 5 * SWP_LD; i += 128) {
        int p = i >> 9;
        int k = i & (SWP_LD - 1);
        float2 v = make_float2(0.f, 0.f);
        if (k < HID)
            v = make_float2(w3g[(2 * p) * HID + k], w3g[(2 * p + 1) * HID + k]);
        swp[i] = v;
    }

    auto issue_stage = [&](int it) {
        const int s  = it & 3;
        const int kb = it * S2_BK;
        unsigned int abase = (unsigned int)__cvta_generic_to_shared(&At[s * S2_TILE]);
        #pragma unroll
        for (int p = 0; p < 4; p++) {
            int idx = tid + p * 128;
            int row = idx >> 2;
            int c   = idx & 3;
            int k0  = kb + c * 4;
            int rem = HID - k0;
            int bytes = rem >= 4 ? 16 : (rem > 0 ? rem * 4 : 0);
            const float* src = g_psp + (size_t)(rbase + row) * HID + (bytes ? k0 : 0);
            unsigned int dst = abase +
                (unsigned int)((row * S2_BK + ((c ^ ((row >> 2) & 3)) * 4)) * 4);
            cp_async16(dst, src, bytes);
        }
        cp_commit();
    };

    ull acc[5] = {0, 0, 0, 0, 0};
    const int asw = (tid >> 2) & 3;

    issue_stage(0);
    issue_stage(1);
    issue_stage(2);

    for (int it = 0; it < S2_T; it++) {
        const int s = it & 3;
        if (it + 3 < S2_T) issue_stage(it + 3);
        cp_wait<3>();
        __syncthreads();

        #pragma unroll
        for (int c = 0; c < 4; c++) {
            float4 a4 = *(const float4*)&At[s * S2_TILE + tid * S2_BK + ((c ^ asw) * 4)];
            const int kg = it * S2_BK + c * 4;
            ull s0 = splat2(a4.x);
            ull s1 = splat2(a4.y);
            ull s2 = splat2(a4.z);
            ull s3 = splat2(a4.w);
            #pragma unroll
            for (int p = 0; p < 5; p++) {
                const float2* pb = swp + p * SWP_LD + kg;
                ulonglong2 w01 = *(const ulonglong2*)(pb);
                ulonglong2 w23 = *(const ulonglong2*)(pb + 2);
                ffma2(acc[p], s0, w01.x);
                ffma2(acc[p], s1, w01.y);
                ffma2(acc[p], s2, w23.x);
                ffma2(acc[p], s3, w23.y);
            }
        }
        __syncthreads();
    }

    // write 10 dots, coalesced-ish float2 stores (8B aligned)
    float* cg = curg + (size_t)(pass * PASS_ROWS + rbase + tid) * NOUT;
    #pragma unroll
    for (int p = 0; p < 5; p++) {
        float lo, hi;
        unpack2(acc[p], lo, hi);
        *(float2*)&cg[2 * p] = make_float2(lo, hi);
    }
}

// ---------------------------------------------------------------------------
// LIF kernel: one block per batch element, 128 threads. Stage cur[b]
// (1000 floats) into smem coalesced; 10 threads run the 100-step chains
// (exact reference op order); write spikes out-layout; coalesced store.
// ---------------------------------------------------------------------------
__global__ __launch_bounds__(128)
void lif_kernel(const float* __restrict__ curg, const float* __restrict__ b3,
                float* __restrict__ out)
{
    __shared__ float sc2[TLEN * NOUT];
    __shared__ float ss[TLEN * NOUT];
    const int b   = blockIdx.x;
    const int tid = threadIdx.x;

    {
        const float4* src = (const float4*)(curg + (size_t)b * TLEN * NOUT);
        float4* dst = (float4*)sc2;
        for (int i = tid; i < (TLEN * NOUT) / 4; i += 128) dst[i] = src[i];
    }
    __syncthreads();

    if (tid < NOUT) {
        const float bb = b3[tid];
        float v = 0.f, s = 0.f;
        float* spk = ss + tid * TLEN;
        #pragma unroll 4
        for (int t = 0; t < TLEN; t++) {
            float cur = __fadd_rn(sc2[t * NOUT + tid], bb);
            float t1  = __fmul_rn(SGF, v);
            float t2  = __fmul_rn(t1, __fsub_rn(1.f, s));
            float vn  = __fadd_rn(t2, cur);
            s = (vn >= 1.f) ? 1.f : 0.f;
            v = vn;
            spk[t] = s;
        }
    }
    __syncthreads();

    {
        const float4* src = (const float4*)ss;
        float4* dst = (float4*)(out + (size_t)b * TLEN * NOUT);
        for (int i = tid; i < (TLEN * NOUT) / 4; i += 128) dst[i] = src[i];
    }
}

#define S2_SMEM ((4 * S2_TILE) * (int)sizeof(float) + 5 * SWP_LD * (int)sizeof(float2))

extern "C" void kernel_launch(void* const* d_in, const int* in_sizes, int n_in,
                              void* d_out, int out_size)
{
    const float* inputs = (const float*)d_in[0];  // [1024, 784]
    const float* w1     = (const float*)d_in[1];  // [500, 784]
    const float* b1     = (const float*)d_in[2];  // [500]
    const float* w2     = (const float*)d_in[3];  // [500, 500]
    const float* b2     = (const float*)d_in[4];  // [500]
    const float* w3     = (const float*)d_in[5];  // [10, 500]
    const float* b3     = (const float*)d_in[6];  // [10]
    float* out          = (float*)d_out;          // [1024, 10, 100]

    float* h_buf;
    float* drive_buf;
    float* cur_buf;
    cudaGetSymbolAddress((void**)&h_buf, g_h);
    cudaGetSymbolAddress((void**)&drive_buf, g_drive);
    cudaGetSymbolAddress((void**)&cur_buf, g_cur);

    cudaFuncSetAttribute(dot_kernel,
                         cudaFuncAttributeMaxDynamicSharedMemorySize, S2_SMEM);

    dim3 blk(128);
    dim3 grd((HID + BN - 1) / BN, BATCH / BM);   // 16 x 16 = 256 blocks
    gemm_bias_act<0><<<grd, blk>>>(inputs, w1, b1, h_buf, BATCH, HID, NIN);
    gemm_bias_act<1><<<grd, blk>>>(h_buf, w2, b2, drive_buf, BATCH, HID, HID);

    for (int pass = 0; pass < NPASS; pass++) {
        psp_kernel<<<PASS_B, 256>>>(pass);
        dot_kernel<<<PASS_ROWS / 128, 128, S2_SMEM>>>(w3, cur_buf, pass);
    }
    lif_kernel<<<BATCH, 128>>>(cur_buf, b3, out);
}